// round 3
// baseline (speedup 1.0000x reference)
#include <cuda_runtime.h>

#define T_STEPS 800
#define UNITS   1024
#define BATCH   32
#define NFEAT   161
#define GRID    128
#define TPB     256
#define CLIPV   20.0f

// rnn tiling: 128 CTAs = 16 k-chunks x 8 col-tiles; each CTA does BOTH dirs,
// staggered so barrier waits hide under the other direction's compute.
#define CK 16
#define CN 8
#define KC 64            // UNITS / CK
#define NC 128           // UNITS / CN

#define SMEM_U_BYTES (KC * NC * 8)        // 65536: U splatted to f32x2 pairs
#define SMEM_H_BYTES (KC * BATCH * 4)     // 8192:  one dir's h chunk
#define SMEM_BYTES   (SMEM_U_BYTES + SMEM_H_BYTES)

__device__ float    g_xw[T_STEPS * UNITS * BATCH];     // [t][u][b]
__device__ float    g_h[2 * UNITS * BATCH];            // [dir][u][b]
__device__ float    g_partF[CK * UNITS * BATCH];       // [kc][u][b]
__device__ float    g_partB[CK * UNITS * BATCH];
__device__ unsigned g_bars[4];                         // F1, B1, F2, B2

typedef unsigned long long ull;

__device__ __forceinline__ void fma2(ull& d, ull a, ull b) {
    asm("fma.rn.f32x2 %0, %1, %2, %0;" : "+l"(d) : "l"(a), "l"(b));
}
__device__ __forceinline__ ull pack2(float v) {
    ull r; asm("mov.b64 %0, {%1, %1};" : "=l"(r) : "f"(v)); return r;
}
__device__ __forceinline__ float2 unpack2(ull v) {
    float2 r; asm("mov.b64 {%0, %1}, %2;" : "=f"(r.x), "=f"(r.y) : "l"(v)); return r;
}

// ---------------------------------------------------------------------------
__global__ void init_kernel() {
    int i = blockIdx.x * blockDim.x + threadIdx.x;
    if (i < 2 * UNITS * BATCH) g_h[i] = 0.0f;
    if (i < 4) g_bars[i] = 0u;
}

// ---------------------------------------------------------------------------
// xw[t][u][b] = sum_f inputs[b][t][f] * W[f][u] + bias[u]
// ---------------------------------------------------------------------------
__global__ void __launch_bounds__(TPB) xw_kernel(const float* __restrict__ inp,
                                                 const float* __restrict__ W,
                                                 const float* __restrict__ bias) {
    __shared__ __align__(16) float in_s[NFEAT * 36];
    const int t   = blockIdx.y;
    const int u0  = blockIdx.x * 128;
    const int tid = threadIdx.x;
    const int bq  = tid & 7;
    const int cq  = tid >> 3;

    for (int idx = tid; idx < BATCH * NFEAT; idx += TPB) {
        int b = idx / NFEAT;
        int f = idx - b * NFEAT;
        in_s[f * 36 + b] = inp[(b * T_STEPS + t) * NFEAT + f];
    }
    __syncthreads();

    ull acc[4][2];
    #pragma unroll
    for (int i = 0; i < 4; i++) { acc[i][0] = 0ull; acc[i][1] = 0ull; }

    const float4* Wp = reinterpret_cast<const float4*>(W) + (u0 >> 2) + cq;
    #pragma unroll 1
    for (int f = 0; f < NFEAT; f++) {
        ulonglong2 ip = *reinterpret_cast<const ulonglong2*>(&in_s[f * 36 + bq * 4]);
        float4 w4 = __ldg(Wp + f * (UNITS / 4));
        ull w0 = pack2(w4.x), w1 = pack2(w4.y), w2 = pack2(w4.z), w3 = pack2(w4.w);
        fma2(acc[0][0], ip.x, w0); fma2(acc[0][1], ip.y, w0);
        fma2(acc[1][0], ip.x, w1); fma2(acc[1][1], ip.y, w1);
        fma2(acc[2][0], ip.x, w2); fma2(acc[2][1], ip.y, w2);
        fma2(acc[3][0], ip.x, w3); fma2(acc[3][1], ip.y, w3);
    }
    #pragma unroll
    for (int i = 0; i < 4; i++) {
        int u = u0 + cq * 4 + i;
        float bu = __ldg(bias + u);
        float2 a0 = unpack2(acc[i][0]);
        float2 a1 = unpack2(acc[i][1]);
        float4 v = make_float4(a0.x + bu, a0.y + bu, a1.x + bu, a1.y + bu);
        *reinterpret_cast<float4*>(&g_xw[(t * UNITS + u) * BATCH + bq * 4]) = v;
    }
}

// ---------------------------------------------------------------------------
// Split arrive/wait monotonic barriers (4 counters).
// arrive: syncthreads (CTA stores done) + release-red by t0.
// wait:   t0 acquire-spin + syncthreads.
// ---------------------------------------------------------------------------
__device__ __forceinline__ void bar_arrive(unsigned* bar) {
    __syncthreads();
    if (threadIdx.x == 0)
        asm volatile("red.release.gpu.global.add.u32 [%0], %1;"
                     :: "l"(bar), "r"(1u) : "memory");
}
__device__ __forceinline__ void bar_wait(unsigned* bar, unsigned target) {
    if (threadIdx.x == 0) {
        unsigned v;
        do {
            asm volatile("ld.acquire.gpu.global.u32 %0, [%1];"
                         : "=r"(v) : "l"(bar) : "memory");
        } while (v < target);
    }
    __syncthreads();
}

// ---------------------------------------------------------------------------
// Persistent bidirectional scan, staggered directions.
// ---------------------------------------------------------------------------
__global__ void __launch_bounds__(TPB, 1) rnn_kernel(const float* __restrict__ Uw,
                                                     float* __restrict__ out) {
    extern __shared__ __align__(16) char smem_raw[];
    ull*   U_dup = reinterpret_cast<ull*>(smem_raw);                   // [64][128] splat
    float* h_s   = reinterpret_cast<float*>(smem_raw + SMEM_U_BYTES);  // [64][32]

    const int tid = threadIdx.x;
    const int bid = blockIdx.x;
    const int kc  = bid >> 3;
    const int nc  = bid & 7;
    const int k0  = kc * KC;
    const int c0  = nc * NC;

    const int bq = tid & 7;     // 8 batch groups of 4
    const int cq = tid >> 3;    // 32 col groups of 4

    // reduction identity (tid < 64): one float4 of h per thread
    const int rq_u  = (bid * 64 + tid) >> 3;   // unit
    const int rq_b4 = tid & 7;                 // batch quad

    // ---- build splatted U tile once: U_dup[k][c] = pack2(U[k0+k][c0+c]) ----
    for (int idx = tid; idx < KC * NC / 4; idx += TPB) {
        int k = idx >> 5, c4 = idx & 31;
        float4 v = __ldg(reinterpret_cast<const float4*>(Uw + (k0 + k) * UNITS + c0) + c4);
        ull* dst = U_dup + k * NC + c4 * 4;
        dst[0] = pack2(v.x); dst[1] = pack2(v.y);
        dst[2] = pack2(v.z); dst[3] = pack2(v.w);
    }

    for (int t = 0; t < T_STEPS; t++) {
        // prefetch x_t for both directions (consumed in reduce steps)
        float4 xf, xb;
        if (tid < 64) {
            xf = __ldcg(reinterpret_cast<const float4*>(
                     g_xw + (t * UNITS + rq_u) * BATCH) + rq_b4);
            xb = __ldcg(reinterpret_cast<const float4*>(
                     g_xw + ((T_STEPS - 1 - t) * UNITS + rq_u) * BATCH) + rq_b4);
        }

        ull acc[4][2];

        // ================= fwd partial GEMM =================
        {
            const float4* src = reinterpret_cast<const float4*>(g_h + k0 * BATCH);
            float4 v0 = __ldcg(src + tid);
            float4 v1 = __ldcg(src + tid + TPB);
            reinterpret_cast<float4*>(h_s)[tid]       = v0;
            reinterpret_cast<float4*>(h_s)[tid + TPB] = v1;
        }
        __syncthreads();
        #pragma unroll
        for (int j = 0; j < 4; j++) { acc[j][0] = 0ull; acc[j][1] = 0ull; }
        {
            const float* hp = h_s + bq * 4;
            const ull*   up = U_dup + cq * 4;
            #pragma unroll 8
            for (int k = 0; k < KC; k++) {
                ulonglong2 h2 = *reinterpret_cast<const ulonglong2*>(hp + k * BATCH);
                ulonglong2 ua = *reinterpret_cast<const ulonglong2*>(up + k * NC);
                ulonglong2 ub = *reinterpret_cast<const ulonglong2*>(up + k * NC + 2);
                fma2(acc[0][0], h2.x, ua.x); fma2(acc[0][1], h2.y, ua.x);
                fma2(acc[1][0], h2.x, ua.y); fma2(acc[1][1], h2.y, ua.y);
                fma2(acc[2][0], h2.x, ub.x); fma2(acc[2][1], h2.y, ub.x);
                fma2(acc[3][0], h2.x, ub.y); fma2(acc[3][1], h2.y, ub.y);
            }
        }
        #pragma unroll
        for (int i = 0; i < 4; i++) {
            float2 a0 = unpack2(acc[i][0]);
            float2 a1 = unpack2(acc[i][1]);
            __stcg(reinterpret_cast<float4*>(
                       g_partF + (kc * UNITS + c0 + cq * 4 + i) * BATCH + bq * 4),
                   make_float4(a0.x, a0.y, a1.x, a1.y));
        }
        bar_arrive(&g_bars[0]);                       // F1

        // ================= bwd partial GEMM =================
        bar_wait(&g_bars[3], (unsigned)t * GRID);     // B2(t-1): hb ready (hidden)
        {
            const float4* src = reinterpret_cast<const float4*>(
                                    g_h + UNITS * BATCH + k0 * BATCH);
            float4 v0 = __ldcg(src + tid);
            float4 v1 = __ldcg(src + tid + TPB);
            reinterpret_cast<float4*>(h_s)[tid]       = v0;
            reinterpret_cast<float4*>(h_s)[tid + TPB] = v1;
        }
        __syncthreads();
        #pragma unroll
        for (int j = 0; j < 4; j++) { acc[j][0] = 0ull; acc[j][1] = 0ull; }
        {
            const float* hp = h_s + bq * 4;
            const ull*   up = U_dup + cq * 4;
            #pragma unroll 8
            for (int k = 0; k < KC; k++) {
                ulonglong2 h2 = *reinterpret_cast<const ulonglong2*>(hp + k * BATCH);
                ulonglong2 ua = *reinterpret_cast<const ulonglong2*>(up + k * NC);
                ulonglong2 ub = *reinterpret_cast<const ulonglong2*>(up + k * NC + 2);
                fma2(acc[0][0], h2.x, ua.x); fma2(acc[0][1], h2.y, ua.x);
                fma2(acc[1][0], h2.x, ua.y); fma2(acc[1][1], h2.y, ua.y);
                fma2(acc[2][0], h2.x, ub.x); fma2(acc[2][1], h2.y, ub.x);
                fma2(acc[3][0], h2.x, ub.y); fma2(acc[3][1], h2.y, ub.y);
            }
        }
        #pragma unroll
        for (int i = 0; i < 4; i++) {
            float2 a0 = unpack2(acc[i][0]);
            float2 a1 = unpack2(acc[i][1]);
            __stcg(reinterpret_cast<float4*>(
                       g_partB + (kc * UNITS + c0 + cq * 4 + i) * BATCH + bq * 4),
                   make_float4(a0.x, a0.y, a1.x, a1.y));
        }
        bar_arrive(&g_bars[1]);                       // B1

        // ================= fwd reduce =================
        bar_wait(&g_bars[0], (unsigned)(t + 1) * GRID);  // F1 (hidden by bwd GEMM)
        if (tid < 64) {
            const float4* pb = reinterpret_cast<const float4*>(g_partF)
                               + rq_u * (BATCH / 4) + rq_b4;
            float4 s = __ldcg(pb);
            #pragma unroll
            for (int j = 1; j < CK; j++) {
                float4 p = __ldcg(pb + j * (UNITS * BATCH / 4));
                s.x += p.x; s.y += p.y; s.z += p.z; s.w += p.w;
            }
            float4 hn;
            hn.x = fminf(fmaxf(xf.x + s.x, 0.f), CLIPV);
            hn.y = fminf(fmaxf(xf.y + s.y, 0.f), CLIPV);
            hn.z = fminf(fmaxf(xf.z + s.z, 0.f), CLIPV);
            hn.w = fminf(fmaxf(xf.w + s.w, 0.f), CLIPV);
            __stcg(reinterpret_cast<float4*>(g_h) + rq_u * (BATCH / 4) + rq_b4, hn);
        }
        bar_arrive(&g_bars[2]);                       // F2

        // ================= bwd reduce =================
        bar_wait(&g_bars[1], (unsigned)(t + 1) * GRID);  // B1 (≈hidden by fwd reduce)
        if (tid < 64) {
            const float4* pb = reinterpret_cast<const float4*>(g_partB)
                               + rq_u * (BATCH / 4) + rq_b4;
            float4 s = __ldcg(pb);
            #pragma unroll
            for (int j = 1; j < CK; j++) {
                float4 p = __ldcg(pb + j * (UNITS * BATCH / 4));
                s.x += p.x; s.y += p.y; s.z += p.z; s.w += p.w;
            }
            float4 hn;
            hn.x = fminf(fmaxf(xb.x + s.x, 0.f), CLIPV);
            hn.y = fminf(fmaxf(xb.y + s.y, 0.f), CLIPV);
            hn.z = fminf(fmaxf(xb.z + s.z, 0.f), CLIPV);
            hn.w = fminf(fmaxf(xb.w + s.w, 0.f), CLIPV);
            __stcg(reinterpret_cast<float4*>(g_h + UNITS * BATCH)
                       + rq_u * (BATCH / 4) + rq_b4, hn);
        }
        bar_arrive(&g_bars[3]);                       // B2

        bar_wait(&g_bars[2], (unsigned)(t + 1) * GRID);  // F2: hf ready for t+1
    }

    bar_wait(&g_bars[3], (unsigned)T_STEPS * GRID);   // hb final globally done

    // epilogue: out[b][u] = hf[u][b] + hb[u][b]
    {
        int o = bid * TPB + tid;
        int b = o >> 10;
        int u = o & 1023;
        out[o] = __ldcg(&g_h[u * BATCH + b]) +
                 __ldcg(&g_h[UNITS * BATCH + u * BATCH + b]);
    }
}

// ---------------------------------------------------------------------------
extern "C" void kernel_launch(void* const* d_in, const int* in_sizes, int n_in,
                              void* d_out, int out_size) {
    const float* inp  = (const float*)d_in[0];  // [32, 800, 161]
    const float* W    = (const float*)d_in[1];  // [161, 1024]
    const float* Uw   = (const float*)d_in[2];  // [1024, 1024]
    const float* bias = (const float*)d_in[3];  // [1024]
    float* out        = (float*)d_out;          // [32, 1024]

    cudaFuncSetAttribute(rnn_kernel, cudaFuncAttributeMaxDynamicSharedMemorySize,
                         SMEM_BYTES);

    init_kernel<<<(2 * UNITS * BATCH + TPB - 1) / TPB, TPB>>>();
    xw_kernel<<<dim3(8, T_STEPS, 1), TPB>>>(inp, W, bias);
    rnn_kernel<<<GRID, TPB, SMEM_BYTES>>>(Uw, out);
}

// round 4
// speedup vs baseline: 1.3785x; 1.3785x over previous
#include <cuda_runtime.h>

#define T_STEPS 800
#define UNITS   1024
#define BATCH   32
#define NFEAT   161
#define GRID    128
#define TPB     256
#define CLIPV   20.0f

// 128 CTAs = 16 k-chunks x 8 col-tiles
#define CK 16
#define CN 8
#define KC 64            // UNITS / CK
#define NC 128           // UNITS / CN

#define SMEM_U_BYTES (KC * NC * 8)        // 65536: U splatted to f32x2 pairs
#define SMEM_H_BYTES (2 * KC * BATCH * 4) // 16384: h chunk, both dirs
#define SMEM_BYTES   (SMEM_U_BYTES + SMEM_H_BYTES)

__device__ float    g_xw[T_STEPS * UNITS * BATCH];          // [t][u][b]
__device__ float    g_part[3][2][CK][UNITS][BATCH];         // triple-buffered partials
__device__ float    g_h[3][2][UNITS][BATCH];                // triple-buffered h
__device__ unsigned g_P[CN];                                // producer counters (16/round)
__device__ unsigned g_C[CK];                                // h-chunk counters (8/round)

typedef unsigned long long ull;

__device__ __forceinline__ void fma2(ull& d, ull a, ull b) {
    asm("fma.rn.f32x2 %0, %1, %2, %0;" : "+l"(d) : "l"(a), "l"(b));
}
__device__ __forceinline__ ull pack2(float v) {
    ull r; asm("mov.b64 %0, {%1, %1};" : "=l"(r) : "f"(v)); return r;
}
__device__ __forceinline__ float2 unpack2(ull v) {
    float2 r; asm("mov.b64 {%0, %1}, %2;" : "=f"(r.x), "=f"(r.y) : "l"(v)); return r;
}

// arrive: all-threads stores done -> release-red by t0
__device__ __forceinline__ void ctr_arrive(unsigned* c) {
    __syncthreads();
    if (threadIdx.x == 0)
        asm volatile("red.release.gpu.global.add.u32 [%0], %1;"
                     :: "l"(c), "r"(1u) : "memory");
}
// wait: t0 acquire-spin, then CTA-wide fence via syncthreads
__device__ __forceinline__ void ctr_wait(unsigned* c, unsigned target) {
    if (threadIdx.x == 0) {
        unsigned v;
        do {
            asm volatile("ld.acquire.gpu.global.u32 %0, [%1];"
                         : "=r"(v) : "l"(c) : "memory");
        } while (v < target);
    }
    __syncthreads();
}

// ---------------------------------------------------------------------------
__global__ void init_kernel() {
    int i = blockIdx.x * blockDim.x + threadIdx.x;
    if (i < 2 * UNITS * BATCH) ((float*)g_h)[i] = 0.0f;   // zero h buf 0
    if (i < CN) g_P[i] = 0u;
    if (i < CK) g_C[i] = 0u;
}

// ---------------------------------------------------------------------------
// xw[t][u][b] = sum_f inputs[b][t][f] * W[f][u] + bias[u]
// ---------------------------------------------------------------------------
__global__ void __launch_bounds__(TPB) xw_kernel(const float* __restrict__ inp,
                                                 const float* __restrict__ W,
                                                 const float* __restrict__ bias) {
    __shared__ __align__(16) float in_s[NFEAT * 36];
    const int t   = blockIdx.y;
    const int u0  = blockIdx.x * 128;
    const int tid = threadIdx.x;
    const int bq  = tid & 7;
    const int cq  = tid >> 3;

    for (int idx = tid; idx < BATCH * NFEAT; idx += TPB) {
        int b = idx / NFEAT;
        int f = idx - b * NFEAT;
        in_s[f * 36 + b] = inp[(b * T_STEPS + t) * NFEAT + f];
    }
    __syncthreads();

    ull acc[4][2];
    #pragma unroll
    for (int i = 0; i < 4; i++) { acc[i][0] = 0ull; acc[i][1] = 0ull; }

    const float4* Wp = reinterpret_cast<const float4*>(W) + (u0 >> 2) + cq;
    #pragma unroll 1
    for (int f = 0; f < NFEAT; f++) {
        ulonglong2 ip = *reinterpret_cast<const ulonglong2*>(&in_s[f * 36 + bq * 4]);
        float4 w4 = __ldg(Wp + f * (UNITS / 4));
        ull w0 = pack2(w4.x), w1 = pack2(w4.y), w2 = pack2(w4.z), w3 = pack2(w4.w);
        fma2(acc[0][0], ip.x, w0); fma2(acc[0][1], ip.y, w0);
        fma2(acc[1][0], ip.x, w1); fma2(acc[1][1], ip.y, w1);
        fma2(acc[2][0], ip.x, w2); fma2(acc[2][1], ip.y, w2);
        fma2(acc[3][0], ip.x, w3); fma2(acc[3][1], ip.y, w3);
    }
    #pragma unroll
    for (int i = 0; i < 4; i++) {
        int u = u0 + cq * 4 + i;
        float bu = __ldg(bias + u);
        float2 a0 = unpack2(acc[i][0]);
        float2 a1 = unpack2(acc[i][1]);
        float4 v = make_float4(a0.x + bu, a0.y + bu, a1.x + bu, a1.y + bu);
        *reinterpret_cast<float4*>(&g_xw[(t * UNITS + u) * BATCH + bq * 4]) = v;
    }
}

// ---------------------------------------------------------------------------
// Persistent bidirectional scan, group-scoped sync.
// CTA (kc,nc): GEMM partial = h[k-chunk kc] @ U[k-chunk kc][col-tile nc],
// both dirs; then reduces the nc-th slice of h-chunk kc (units 64kc+8nc..+8).
// ---------------------------------------------------------------------------
__global__ void __launch_bounds__(TPB, 1) rnn_kernel(const float* __restrict__ Uw,
                                                     float* __restrict__ out) {
    extern __shared__ __align__(16) char smem_raw[];
    ull*   U_dup = reinterpret_cast<ull*>(smem_raw);                   // [64][128] splat
    float* h_s   = reinterpret_cast<float*>(smem_raw + SMEM_U_BYTES);  // [2][64][32]

    const int tid = threadIdx.x;
    const int bid = blockIdx.x;
    const int kc  = bid >> 3;
    const int nc  = bid & 7;
    const int k0  = kc * KC;
    const int c0  = nc * NC;

    const int bq = tid & 7;     // 8 batch groups of 4
    const int cq = tid >> 3;    // 32 col groups of 4

    // reduce identity (tid < 128): (dir, u_local 0..7, batch-quad 0..7)
    const int rdir = tid >> 6;
    const int ru   = k0 + nc * 8 + ((tid >> 3) & 7);
    const int rb4  = tid & 7;

    // ---- build splatted U tile once ----
    for (int idx = tid; idx < KC * NC / 4; idx += TPB) {
        int k = idx >> 5, c4 = idx & 31;
        float4 v = __ldg(reinterpret_cast<const float4*>(Uw + (k0 + k) * UNITS + c0) + c4);
        ull* dst = U_dup + k * NC + c4 * 4;
        dst[0] = pack2(v.x); dst[1] = pack2(v.y);
        dst[2] = pack2(v.z); dst[3] = pack2(v.w);
    }

    // ---- pre-stage h_{-1} = zeros from g_h buf 0 ----
    #pragma unroll
    for (int j = 0; j < 4; j++) {
        int idx = tid + j * TPB;
        int dir = idx >> 9, off = idx & 511;
        reinterpret_cast<float4*>(h_s)[idx] =
            __ldcg(reinterpret_cast<const float4*>(&g_h[0][dir][k0][0]) + off);
    }
    __syncthreads();

    int pb = 0;   // partial buffer = t % 3

    for (int t = 0; t < T_STEPS; t++) {
        int hb = pb + 1; if (hb == 3) hb = 0;   // h buffer = (t+1) % 3

        // prefetch x for this round's reduce (used ~4000 cyc later)
        float4 xv;
        if (tid < 128) {
            int xt = rdir ? (T_STEPS - 1 - t) : t;
            xv = __ldcg(reinterpret_cast<const float4*>(
                     g_xw + (xt * UNITS + ru) * BATCH) + rb4);
        }

        // ---- fused GEMM (both dirs) ----
        ull acc[2][4][2];
        #pragma unroll
        for (int d = 0; d < 2; d++)
            #pragma unroll
            for (int i = 0; i < 4; i++) { acc[d][i][0] = 0ull; acc[d][i][1] = 0ull; }
        {
            const float* hp = h_s + bq * 4;
            const ull*   up = U_dup + cq * 4;
            #pragma unroll 8
            for (int k = 0; k < KC; k++) {
                ulonglong2 h0 = *reinterpret_cast<const ulonglong2*>(hp + k * BATCH);
                ulonglong2 h1 = *reinterpret_cast<const ulonglong2*>(hp + KC * BATCH + k * BATCH);
                ulonglong2 ua = *reinterpret_cast<const ulonglong2*>(up + k * NC);
                ulonglong2 ub = *reinterpret_cast<const ulonglong2*>(up + k * NC + 2);
                fma2(acc[0][0][0], h0.x, ua.x); fma2(acc[0][0][1], h0.y, ua.x);
                fma2(acc[0][1][0], h0.x, ua.y); fma2(acc[0][1][1], h0.y, ua.y);
                fma2(acc[0][2][0], h0.x, ub.x); fma2(acc[0][2][1], h0.y, ub.x);
                fma2(acc[0][3][0], h0.x, ub.y); fma2(acc[0][3][1], h0.y, ub.y);
                fma2(acc[1][0][0], h1.x, ua.x); fma2(acc[1][0][1], h1.y, ua.x);
                fma2(acc[1][1][0], h1.x, ua.y); fma2(acc[1][1][1], h1.y, ua.y);
                fma2(acc[1][2][0], h1.x, ub.x); fma2(acc[1][2][1], h1.y, ub.x);
                fma2(acc[1][3][0], h1.x, ub.y); fma2(acc[1][3][1], h1.y, ub.y);
            }
        }

        // ---- store partials (triple-buffered; safe: global skew <= 2 rounds) ----
        #pragma unroll
        for (int d = 0; d < 2; d++)
            #pragma unroll
            for (int i = 0; i < 4; i++) {
                float2 a0 = unpack2(acc[d][i][0]);
                float2 a1 = unpack2(acc[d][i][1]);
                __stcg(reinterpret_cast<float4*>(
                           &g_part[pb][d][kc][c0 + cq * 4 + i][bq * 4]),
                       make_float4(a0.x, a0.y, a1.x, a1.y));
            }
        ctr_arrive(&g_P[nc]);

        // ---- wait for the 16 producers of our h-chunk's partials ----
        ctr_wait(&g_P[kc >> 1], 16u * (t + 1));

        // ---- reduce own slice: units [64kc+8nc, +8), both dirs ----
        if (tid < 128) {
            const float4* base = reinterpret_cast<const float4*>(
                                     &g_part[pb][rdir][0][ru][0]) + rb4;
            float4 s = __ldcg(base);
            #pragma unroll
            for (int j = 1; j < CK; j++) {
                float4 p = __ldcg(base + j * (UNITS * BATCH / 4));
                s.x += p.x; s.y += p.y; s.z += p.z; s.w += p.w;
            }
            float4 hn;
            hn.x = fminf(fmaxf(xv.x + s.x, 0.f), CLIPV);
            hn.y = fminf(fmaxf(xv.y + s.y, 0.f), CLIPV);
            hn.z = fminf(fmaxf(xv.z + s.z, 0.f), CLIPV);
            hn.w = fminf(fmaxf(xv.w + s.w, 0.f), CLIPV);
            __stcg(reinterpret_cast<float4*>(&g_h[hb][rdir][ru][0]) + rb4, hn);
        }
        ctr_arrive(&g_C[kc]);

        // ---- wait for own 8-CTA group (tightly clustered: same P release) ----
        ctr_wait(&g_C[kc], 8u * (t + 1));

        // ---- stage h_t for next round ----
        #pragma unroll
        for (int j = 0; j < 4; j++) {
            int idx = tid + j * TPB;
            int dir = idx >> 9, off = idx & 511;
            reinterpret_cast<float4*>(h_s)[idx] =
                __ldcg(reinterpret_cast<const float4*>(&g_h[hb][dir][k0][0]) + off);
        }
        __syncthreads();

        pb = hb;
    }

    // epilogue: h_799 (both dirs) sits in h_s; one CTA per k-chunk writes out
    if (nc == 0) {
        #pragma unroll
        for (int i = 0; i < 8; i++) {
            int idx = tid + i * TPB;            // 2048 = 32b x 64k
            int b = idx >> 6, k = idx & 63;
            out[b * UNITS + k0 + k] = h_s[k * BATCH + b] +
                                      h_s[KC * BATCH + k * BATCH + b];
        }
    }
}

// ---------------------------------------------------------------------------
extern "C" void kernel_launch(void* const* d_in, const int* in_sizes, int n_in,
                              void* d_out, int out_size) {
    const float* inp  = (const float*)d_in[0];  // [32, 800, 161]
    const float* W    = (const float*)d_in[1];  // [161, 1024]
    const float* Uw   = (const float*)d_in[2];  // [1024, 1024]
    const float* bias = (const float*)d_in[3];  // [1024]
    float* out        = (float*)d_out;          // [32, 1024]

    cudaFuncSetAttribute(rnn_kernel, cudaFuncAttributeMaxDynamicSharedMemorySize,
                         SMEM_BYTES);

    init_kernel<<<(2 * UNITS * BATCH + TPB - 1) / TPB, TPB>>>();
    xw_kernel<<<dim3(8, T_STEPS, 1), TPB>>>(inp, W, bias);
    rnn_kernel<<<GRID, TPB, SMEM_BYTES>>>(Uw, out);
}

// round 5
// speedup vs baseline: 1.5188x; 1.1018x over previous
#include <cuda_runtime.h>

#define T_STEPS 800
#define UNITS   1024
#define BATCH   32
#define NFEAT   161
#define GRID    128
#define TPB     256     // xw kernel
#define TPR     128     // rnn kernel
#define CLIPV   20.0f

// 128 CTAs = 16 k-chunks x 8 col-tiles
#define CK 16
#define CN 8
#define KC 64            // UNITS / CK
#define NC 128           // UNITS / CN

#define SMEM_U_BYTES (KC * NC * 4)        // 32768: U tile, natural fp32
#define SMEM_H_BYTES (2 * KC * BATCH * 4) // 16384: h chunk, both dirs
#define SMEM_BYTES   (SMEM_U_BYTES + SMEM_H_BYTES)

__device__ float    g_xw[T_STEPS * UNITS * BATCH];          // [t][u][b]
__device__ float    g_part[3][2][CK][UNITS][BATCH];         // triple-buffered partials
__device__ float    g_h[3][2][UNITS][BATCH];                // triple-buffered h
__device__ unsigned g_P[CN];                                // producer counters (16/round)
__device__ unsigned g_C[CK];                                // h-chunk counters (8/round)

typedef unsigned long long ull;

__device__ __forceinline__ void fma2(ull& d, ull a, ull b) {
    asm("fma.rn.f32x2 %0, %1, %2, %0;" : "+l"(d) : "l"(a), "l"(b));
}
__device__ __forceinline__ ull pack2(float v) {
    ull r; asm("mov.b64 %0, {%1, %1};" : "=l"(r) : "f"(v)); return r;
}
__device__ __forceinline__ float2 unpack2(ull v) {
    float2 r; asm("mov.b64 {%0, %1}, %2;" : "=f"(r.x), "=f"(r.y) : "l"(v)); return r;
}

__device__ __forceinline__ void ctr_arrive(unsigned* c) {
    __syncthreads();
    if (threadIdx.x == 0)
        asm volatile("red.release.gpu.global.add.u32 [%0], %1;"
                     :: "l"(c), "r"(1u) : "memory");
}
__device__ __forceinline__ void ctr_wait(unsigned* c, unsigned target) {
    if (threadIdx.x == 0) {
        unsigned v;
        do {
            asm volatile("ld.acquire.gpu.global.u32 %0, [%1];"
                         : "=r"(v) : "l"(c) : "memory");
        } while (v < target);
    }
    __syncthreads();
}

// ---------------------------------------------------------------------------
__global__ void init_kernel() {
    int i = blockIdx.x * blockDim.x + threadIdx.x;
    if (i < 2 * UNITS * BATCH) ((float*)g_h)[i] = 0.0f;   // zero h buf 0
    if (i < CN) g_P[i] = 0u;
    if (i < CK) g_C[i] = 0u;
}

// ---------------------------------------------------------------------------
// xw[t][u][b] = sum_f inputs[b][t][f] * W[f][u] + bias[u]
// ---------------------------------------------------------------------------
__global__ void __launch_bounds__(TPB) xw_kernel(const float* __restrict__ inp,
                                                 const float* __restrict__ W,
                                                 const float* __restrict__ bias) {
    __shared__ __align__(16) float in_s[NFEAT * 36];
    const int t   = blockIdx.y;
    const int u0  = blockIdx.x * 128;
    const int tid = threadIdx.x;
    const int bq  = tid & 7;
    const int cq  = tid >> 3;

    for (int idx = tid; idx < BATCH * NFEAT; idx += TPB) {
        int b = idx / NFEAT;
        int f = idx - b * NFEAT;
        in_s[f * 36 + b] = inp[(b * T_STEPS + t) * NFEAT + f];
    }
    __syncthreads();

    ull acc[4][2];
    #pragma unroll
    for (int i = 0; i < 4; i++) { acc[i][0] = 0ull; acc[i][1] = 0ull; }

    const float4* Wp = reinterpret_cast<const float4*>(W) + (u0 >> 2) + cq;
    #pragma unroll 1
    for (int f = 0; f < NFEAT; f++) {
        ulonglong2 ip = *reinterpret_cast<const ulonglong2*>(&in_s[f * 36 + bq * 4]);
        float4 w4 = __ldg(Wp + f * (UNITS / 4));
        ull w0 = pack2(w4.x), w1 = pack2(w4.y), w2 = pack2(w4.z), w3 = pack2(w4.w);
        fma2(acc[0][0], ip.x, w0); fma2(acc[0][1], ip.y, w0);
        fma2(acc[1][0], ip.x, w1); fma2(acc[1][1], ip.y, w1);
        fma2(acc[2][0], ip.x, w2); fma2(acc[2][1], ip.y, w2);
        fma2(acc[3][0], ip.x, w3); fma2(acc[3][1], ip.y, w3);
    }
    #pragma unroll
    for (int i = 0; i < 4; i++) {
        int u = u0 + cq * 4 + i;
        float bu = __ldg(bias + u);
        float2 a0 = unpack2(acc[i][0]);
        float2 a1 = unpack2(acc[i][1]);
        float4 v = make_float4(a0.x + bu, a0.y + bu, a1.x + bu, a1.y + bu);
        *reinterpret_cast<float4*>(&g_xw[(t * UNITS + u) * BATCH + bq * 4]) = v;
    }
}

// ---------------------------------------------------------------------------
// Persistent bidirectional scan. 128 threads/CTA; per-thread tile
// 2dir x 4batch x 8col, full k=64: 4 LDS.128 + 8 MOV + 32 FFMA2 per k
// -> 1 B/MAC -> LDS crossbar = FFMA2 pipe floor (4096 cyc/round).
// ---------------------------------------------------------------------------
__global__ void __launch_bounds__(TPR, 1) rnn_kernel(const float* __restrict__ Uw,
                                                     float* __restrict__ out) {
    extern __shared__ __align__(16) char smem_raw[];
    float* U_s = reinterpret_cast<float*>(smem_raw);                   // [64][128]
    float* h_s = reinterpret_cast<float*>(smem_raw + SMEM_U_BYTES);    // [2][64][32]

    const int tid = threadIdx.x;
    const int bid = blockIdx.x;
    const int kc  = bid >> 3;
    const int nc  = bid & 7;
    const int k0  = kc * KC;
    const int c0  = nc * NC;

    const int b0 = (tid & 7) * 4;        // 8 batch groups of 4
    const int cc = (tid >> 3) * 8;       // 16 col groups of 8

    // reduce identity: (dir, u_local 0..7, batch-quad 0..7)
    const int rdir = tid >> 6;
    const int ru   = k0 + nc * 8 + ((tid >> 3) & 7);
    const int rb4  = tid & 7;

    // ---- load natural U tile once (32 KB) ----
    for (int idx = tid; idx < KC * NC / 4; idx += TPR) {
        reinterpret_cast<float4*>(U_s)[idx] =
            __ldg(reinterpret_cast<const float4*>(Uw + k0 * UNITS + c0
                      + (idx >> 5) * UNITS) + (idx & 31));
    }

    // ---- pre-stage h_{-1} = zeros ----
    #pragma unroll
    for (int j = 0; j < 8; j++) {
        int idx = tid + j * TPR;
        int dir = idx >> 9, off = idx & 511;
        reinterpret_cast<float4*>(h_s)[idx] =
            __ldcg(reinterpret_cast<const float4*>(&g_h[0][dir][k0][0]) + off);
    }
    __syncthreads();

    int pb = 0;   // partial buffer = t % 3

    for (int t = 0; t < T_STEPS; t++) {
        int hb = pb + 1; if (hb == 3) hb = 0;

        // prefetch x for this round's reduce
        int xt = rdir ? (T_STEPS - 1 - t) : t;
        float4 xv = __ldcg(reinterpret_cast<const float4*>(
                        g_xw + (xt * UNITS + ru) * BATCH) + rb4);

        // ---- fused GEMM (both dirs), acc[dir][bpair][col] ----
        ull acc[2][2][8];
        #pragma unroll
        for (int d = 0; d < 2; d++)
            #pragma unroll
            for (int p = 0; p < 2; p++)
                #pragma unroll
                for (int i = 0; i < 8; i++) acc[d][p][i] = 0ull;
        {
            const float* hp = h_s + b0;
            const float* up = U_s + cc;
            #pragma unroll 8
            for (int k = 0; k < KC; k++) {
                ulonglong2 hA = *reinterpret_cast<const ulonglong2*>(hp + k * BATCH);
                ulonglong2 hB = *reinterpret_cast<const ulonglong2*>(hp + KC * BATCH + k * BATCH);
                float4 uA = *reinterpret_cast<const float4*>(up + k * NC);
                float4 uB = *reinterpret_cast<const float4*>(up + k * NC + 4);
                ull s0 = pack2(uA.x), s1 = pack2(uA.y), s2 = pack2(uA.z), s3 = pack2(uA.w);
                ull s4 = pack2(uB.x), s5 = pack2(uB.y), s6 = pack2(uB.z), s7 = pack2(uB.w);
                fma2(acc[0][0][0], hA.x, s0); fma2(acc[0][1][0], hA.y, s0);
                fma2(acc[0][0][1], hA.x, s1); fma2(acc[0][1][1], hA.y, s1);
                fma2(acc[0][0][2], hA.x, s2); fma2(acc[0][1][2], hA.y, s2);
                fma2(acc[0][0][3], hA.x, s3); fma2(acc[0][1][3], hA.y, s3);
                fma2(acc[0][0][4], hA.x, s4); fma2(acc[0][1][4], hA.y, s4);
                fma2(acc[0][0][5], hA.x, s5); fma2(acc[0][1][5], hA.y, s5);
                fma2(acc[0][0][6], hA.x, s6); fma2(acc[0][1][6], hA.y, s6);
                fma2(acc[0][0][7], hA.x, s7); fma2(acc[0][1][7], hA.y, s7);
                fma2(acc[1][0][0], hB.x, s0); fma2(acc[1][1][0], hB.y, s0);
                fma2(acc[1][0][1], hB.x, s1); fma2(acc[1][1][1], hB.y, s1);
                fma2(acc[1][0][2], hB.x, s2); fma2(acc[1][1][2], hB.y, s2);
                fma2(acc[1][0][3], hB.x, s3); fma2(acc[1][1][3], hB.y, s3);
                fma2(acc[1][0][4], hB.x, s4); fma2(acc[1][1][4], hB.y, s4);
                fma2(acc[1][0][5], hB.x, s5); fma2(acc[1][1][5], hB.y, s5);
                fma2(acc[1][0][6], hB.x, s6); fma2(acc[1][1][6], hB.y, s6);
                fma2(acc[1][0][7], hB.x, s7); fma2(acc[1][1][7], hB.y, s7);
            }
        }

        // ---- store partials: [pb][d][kc][col][batch], float4 coalesced ----
        #pragma unroll
        for (int d = 0; d < 2; d++)
            #pragma unroll
            for (int i = 0; i < 8; i++) {
                float2 a0 = unpack2(acc[d][0][i]);
                float2 a1 = unpack2(acc[d][1][i]);
                __stcg(reinterpret_cast<float4*>(
                           &g_part[pb][d][kc][c0 + cc + i][b0]),
                       make_float4(a0.x, a0.y, a1.x, a1.y));
            }
        ctr_arrive(&g_P[nc]);

        // ---- wait for the 16 producers of our h-chunk's partials ----
        ctr_wait(&g_P[kc >> 1], 16u * (t + 1));

        // ---- reduce own slice: units [64kc+8nc, +8), both dirs ----
        {
            const float4* base = reinterpret_cast<const float4*>(
                                     &g_part[pb][rdir][0][ru][0]) + rb4;
            float4 s = __ldcg(base);
            #pragma unroll
            for (int j = 1; j < CK; j++) {
                float4 p = __ldcg(base + j * (UNITS * BATCH / 4));
                s.x += p.x; s.y += p.y; s.z += p.z; s.w += p.w;
            }
            float4 hn;
            hn.x = fminf(fmaxf(xv.x + s.x, 0.f), CLIPV);
            hn.y = fminf(fmaxf(xv.y + s.y, 0.f), CLIPV);
            hn.z = fminf(fmaxf(xv.z + s.z, 0.f), CLIPV);
            hn.w = fminf(fmaxf(xv.w + s.w, 0.f), CLIPV);
            __stcg(reinterpret_cast<float4*>(&g_h[hb][rdir][ru][0]) + rb4, hn);
        }
        ctr_arrive(&g_C[kc]);

        // ---- wait for own 8-CTA group, then stage h_t ----
        ctr_wait(&g_C[kc], 8u * (t + 1));
        #pragma unroll
        for (int j = 0; j < 8; j++) {
            int idx = tid + j * TPR;
            int dir = idx >> 9, off = idx & 511;
            reinterpret_cast<float4*>(h_s)[idx] =
                __ldcg(reinterpret_cast<const float4*>(&g_h[hb][dir][k0][0]) + off);
        }
        __syncthreads();

        pb = hb;
    }

    // epilogue: h_799 (both dirs) sits in h_s; one CTA per k-chunk writes out
    if (nc == 0) {
        #pragma unroll
        for (int i = 0; i < 16; i++) {
            int idx = tid + i * TPR;            // 2048 = 32b x 64k
            int b = idx >> 6, k = idx & 63;
            out[b * UNITS + k0 + k] = h_s[k * BATCH + b] +
                                      h_s[KC * BATCH + k * BATCH + b];
        }
    }
}

// ---------------------------------------------------------------------------
extern "C" void kernel_launch(void* const* d_in, const int* in_sizes, int n_in,
                              void* d_out, int out_size) {
    const float* inp  = (const float*)d_in[0];  // [32, 800, 161]
    const float* W    = (const float*)d_in[1];  // [161, 1024]
    const float* Uw   = (const float*)d_in[2];  // [1024, 1024]
    const float* bias = (const float*)d_in[3];  // [1024]
    float* out        = (float*)d_out;          // [32, 1024]

    cudaFuncSetAttribute(rnn_kernel, cudaFuncAttributeMaxDynamicSharedMemorySize,
                         SMEM_BYTES);

    init_kernel<<<(2 * UNITS * BATCH + TPB - 1) / TPB, TPB>>>();
    xw_kernel<<<dim3(8, T_STEPS, 1), TPB>>>(inp, W, bias);
    rnn_kernel<<<GRID, TPR, SMEM_BYTES>>>(Uw, out);
}